// round 1
// baseline (speedup 1.0000x reference)
#include <cuda_runtime.h>

// YOLOv2 loss, B=64, A=5, C=80, G=32, N=50.
#define NBATCH 64
#define NA 5
#define NC 80
#define GDIM 32
#define NGT 50
#define NBOX (NA*GDIM*GDIM)          // 5120
#define NCH  (5+NC)                  // 85
#define P2_BLOCKS (NBATCH*NBOX/256)  // 1280
#define P3_BLOCKS (NBATCH*NGT/4)     // 800 (4 warps per block)

// ---------------- scratch (no allocations allowed) ----------------
__device__ float4 g_gtbox[NBATCH*NGT];   // gt box xyxy
__device__ float2 g_gtsa[NBATCH*NGT];    // {area, 0.6*area}
__device__ int    g_bbox[NBATCH*NGT];    // best box index within batch
__device__ float4 g_enc[NBATCH*NGT];     // regression targets
__device__ float  g_iou_t[NBATCH*NGT];   // IoU(gt n, pred at best box)
__device__ float  g_p2_noobj[P2_BLOCKS];
__device__ float  g_p2_prior[P2_BLOCKS];
__device__ float  g_p3_coord[P3_BLOCKS];
__device__ float  g_p3_obj[P3_BLOCKS];
__device__ float  g_p3_cls[P3_BLOCKS];

__device__ __forceinline__ float sigmoidf_(float x) {
    return 1.0f / (1.0f + __expf(-x));
}

// ---------------- phase 1: per-GT prep (3200 items) ----------------
__global__ void prep_kernel(const float* __restrict__ gt,
                            const float* __restrict__ anc) {
    int i = blockIdx.x * blockDim.x + threadIdx.x;
    if (i >= NBATCH * NGT) return;
    const float* g = gt + (size_t)i * 7;
    float dx = g[0], dy = g[1], gx = g[2], gy = g[3], gw = g[4], gh = g[5];
    float ga = gw * gh;
    float best = -1.0f; int bp = 0;
    #pragma unroll
    for (int a = 0; a < NA; a++) {
        float aw = anc[2*a], ah = anc[2*a+1];
        float inter = fminf(gw, aw) * fminf(gh, ah);
        float iou = inter / (ga + aw * ah - inter);
        if (iou > best) { best = iou; bp = a; }
    }
    int gxi = (int)gx, gyi = (int)gy;
    g_bbox[i] = bp * (GDIM*GDIM) + gyi * GDIM + gxi;

    float cx = dx + gx * (1.0f/32.0f);
    float cy = dy + gy * (1.0f/32.0f);
    float4 box;
    box.x = cx - 0.5f*gw; box.y = cy - 0.5f*gh;
    box.z = cx + 0.5f*gw; box.w = cy + 0.5f*gh;
    g_gtbox[i] = box;
    g_gtsa[i]  = make_float2(ga, 0.6f * ga);

    float4 enc;
    enc.x = dx; enc.y = dy;
    enc.z = logf(gw) - logf(anc[2*bp]);
    enc.w = logf(gh) - logf(anc[2*bp+1]);
    g_enc[i] = enc;
}

// ---------------- phase 2: main per-box kernel ----------------
// One thread per (b, a, y, x) box. Division-free IoU>0.6 test:
//   inter/(sa+sb-inter) > 0.6  <=>  1.6*inter > 0.6*sa + 0.6*sb
__global__ void __launch_bounds__(256) main_kernel(const float* __restrict__ pred,
                                                   const float* __restrict__ anc) {
    __shared__ float4 sbox[NGT];
    __shared__ float2 ssa[NGT];
    __shared__ int    sbb[NGT];
    __shared__ float  red[256];

    int b   = blockIdx.x / 20;            // 20 blocks of 256 = 5120 boxes
    int idx = (blockIdx.x % 20) * 256 + threadIdx.x;

    if (threadIdx.x < NGT) {
        int gi = b * NGT + threadIdx.x;
        sbox[threadIdx.x] = g_gtbox[gi];
        ssa[threadIdx.x]  = g_gtsa[gi];
        sbb[threadIdx.x]  = g_bbox[gi];
    }
    __syncthreads();

    int a    = idx >> 10;
    int cell = idx & 1023;
    const float* pp = pred + (((size_t)(b * (NA*NCH) + a * NCH)) << 10) + cell;
    float dx = pp[0];
    float dy = pp[1 << 10];
    float tw = pp[2 << 10];
    float th = pp[3 << 10];
    float to = pp[4 << 10];

    float sdx = sigmoidf_(dx), sdy = sigmoidf_(dy), sobj = sigmoidf_(to);
    int x = cell & 31, y = cell >> 5;
    float cx = sdx + (float)x * (1.0f/32.0f);
    float cy = sdy + (float)y * (1.0f/32.0f);
    float aw = anc[2*a], ah = anc[2*a+1];
    float pw = aw * __expf(tw), ph = ah * __expf(th);
    float hx = 0.5f*pw, hy = 0.5f*ph;
    float bx1 = cx - hx, by1 = cy - hy, bx2 = cx + hx, by2 = cy + hy;
    float sb = pw * ph, tsb = 0.6f * sb;

    bool isbest = false, over = false;
    #pragma unroll 5
    for (int n = 0; n < NGT; n++) {
        float4 gb = sbox[n];
        float w = fminf(bx2, gb.z) - fmaxf(bx1, gb.x);
        float h = fminf(by2, gb.w) - fmaxf(by1, gb.y);
        w = fmaxf(w, 0.0f); h = fmaxf(h, 0.0f);
        float inter = w * h;
        float2 s2 = ssa[n];
        over = over || (1.6f * inter > s2.y + tsb);
        if (idx == sbb[n]) {
            isbest = true;
            g_iou_t[b * NGT + n] = inter / (s2.x + sb - inter);
        }
    }

    float noobj = (!isbest && !over) ? sobj * sobj : 0.0f;
    float prior = 0.0f;
    if (!isbest) {
        float d0 = sdx - 0.015625f, d1 = sdy - 0.015625f;
        prior = d0*d0 + d1*d1 + tw*tw + th*th;
    }

    // deterministic block reductions
    red[threadIdx.x] = noobj; __syncthreads();
    for (int s = 128; s > 0; s >>= 1) {
        if (threadIdx.x < s) red[threadIdx.x] += red[threadIdx.x + s];
        __syncthreads();
    }
    if (threadIdx.x == 0) g_p2_noobj[blockIdx.x] = red[0];
    __syncthreads();
    red[threadIdx.x] = prior; __syncthreads();
    for (int s = 128; s > 0; s >>= 1) {
        if (threadIdx.x < s) red[threadIdx.x] += red[threadIdx.x + s];
        __syncthreads();
    }
    if (threadIdx.x == 0) g_p2_prior[blockIdx.x] = red[0];
}

// ---------------- phase 3: gathered-row loss (warp per GT) ----------------
// cls = sum_c (softmax_c - onehot_c)^2 = Q/S^2 - 2*e_k/S + 1  (one pass)
__global__ void __launch_bounds__(128) gather_kernel(const float* __restrict__ pred,
                                                     const float* __restrict__ gt) {
    int warp = threadIdx.x >> 5;
    int lane = threadIdx.x & 31;
    int gtid = blockIdx.x * 4 + warp;     // < 3200 exactly
    int b = gtid / NGT;
    int bbox = g_bbox[gtid];
    int a = bbox >> 10, cell = bbox & 1023;
    const float* pp = pred + (((size_t)(b * (NA*NCH) + a * NCH)) << 10) + cell;
    int k = (int)gt[(size_t)gtid * 7 + 6];

    float S = 0.0f, Q = 0.0f, ek = 0.0f;
    for (int c = lane; c < NC; c += 32) {
        float e = __expf(pp[(size_t)(5 + c) << 10]);
        S += e; Q += e * e;
        if (c == k) ek = e;
    }
    #pragma unroll
    for (int off = 16; off; off >>= 1) {
        S  += __shfl_xor_sync(0xffffffffu, S,  off);
        Q  += __shfl_xor_sync(0xffffffffu, Q,  off);
        ek += __shfl_xor_sync(0xffffffffu, ek, off);
    }

    __shared__ float sc[4], so[4], sl[4];
    if (lane == 0) {
        float sdx = sigmoidf_(pp[0]);
        float sdy = sigmoidf_(pp[1 << 10]);
        float tw  = pp[2 << 10], th = pp[3 << 10];
        float sobj = sigmoidf_(pp[4 << 10]);
        float4 enc = g_enc[gtid];
        float d0 = sdx - enc.x, d1 = sdy - enc.y, d2 = tw - enc.z, d3 = th - enc.w;
        sc[warp] = d0*d0 + d1*d1 + d2*d2 + d3*d3;
        float di = sobj - g_iou_t[gtid];
        so[warp] = di * di;
        float invS = 1.0f / S;
        sl[warp] = Q * invS * invS - 2.0f * ek * invS + 1.0f;
    }
    __syncthreads();
    if (threadIdx.x == 0) {
        g_p3_coord[blockIdx.x] = sc[0] + sc[1] + sc[2] + sc[3];
        g_p3_obj[blockIdx.x]   = so[0] + so[1] + so[2] + so[3];
        g_p3_cls[blockIdx.x]   = sl[0] + sl[1] + sl[2] + sl[3];
    }
}

// ---------------- phase 4: deterministic final combine ----------------
__global__ void final_kernel(float* __restrict__ out, const int* __restrict__ seen) {
    __shared__ float red[256];
    __shared__ float total[5];
    int t = threadIdx.x;
    float acc[5] = {0.f, 0.f, 0.f, 0.f, 0.f};
    for (int i = t; i < P2_BLOCKS; i += 256) {
        acc[0] += g_p2_noobj[i];
        acc[1] += g_p2_prior[i];
    }
    for (int i = t; i < P3_BLOCKS; i += 256) {
        acc[2] += g_p3_coord[i];
        acc[3] += g_p3_obj[i];
        acc[4] += g_p3_cls[i];
    }
    #pragma unroll
    for (int c = 0; c < 5; c++) {
        red[t] = acc[c]; __syncthreads();
        for (int s = 128; s > 0; s >>= 1) {
            if (t < s) red[t] += red[t + s];
            __syncthreads();
        }
        if (t == 0) total[c] = red[0];
        __syncthreads();
    }
    if (t == 0) {
        float lp = (seen[0] < 12800) ? 0.01f : 0.0f;
        // loss = cls + 1*noobj + 5*obj + 1*coord + 0.01*prior(if seen<thr)
        out[0] = total[4] + total[0] + 5.0f * total[3] + total[2] + lp * total[1];
    }
}

extern "C" void kernel_launch(void* const* d_in, const int* in_sizes, int n_in,
                              void* d_out, int out_size) {
    const float* pred = (const float*)d_in[0];
    const float* gt   = (const float*)d_in[1];
    const float* anc  = (const float*)d_in[2];
    const int*   seen = (const int*)d_in[3];
    (void)in_sizes; (void)n_in; (void)out_size;

    prep_kernel<<<(NBATCH*NGT + 127) / 128, 128>>>(gt, anc);
    main_kernel<<<P2_BLOCKS, 256>>>(pred, anc);
    gather_kernel<<<P3_BLOCKS, 128>>>(pred, gt);
    final_kernel<<<1, 256>>>((float*)d_out, seen);
}

// round 3
// speedup vs baseline: 1.6650x; 1.6650x over previous
#include <cuda_runtime.h>

// YOLOv2 loss, B=64, A=5, C=80, G=32, N=50.
#define NBATCH 64
#define NGT 50
#define MAIN_BLOCKS 640          // 64 batches x 10 segs of 512 boxes (2 boxes/thread)
#define GATH_BLOCKS 400          // 3200 GTs / 8 warps per 256-thread block
#define TOTAL_BLOCKS (MAIN_BLOCKS + GATH_BLOCKS)

__device__ float g_noobj[MAIN_BLOCKS];
__device__ float g_prior[MAIN_BLOCKS];
__device__ float g_coord[GATH_BLOCKS];
__device__ float g_obj[GATH_BLOCKS];
__device__ float g_cls[GATH_BLOCKS];

__device__ __forceinline__ float sigm(float x) { return 1.0f / (1.0f + __expf(-x)); }

__global__ void __launch_bounds__(256) fused_kernel(const float* __restrict__ pred,
                                                    const float* __restrict__ gt,
                                                    const float* __restrict__ anc)
{
    int tid = threadIdx.x;

    if (blockIdx.x < MAIN_BLOCKS) {
        // ============== MAIN PATH: noobj + prior over all 327680 boxes ==============
        __shared__ float4 sbox[NGT];
        __shared__ float  ssa6[NGT];        // 0.6 * gt area
        __shared__ unsigned char flag[512]; // best-box marks for this block's range
        __shared__ float  sred[16];

        int b    = blockIdx.x / 10;
        int base = (blockIdx.x % 10) * 512;
        int idx0 = base + tid, idx1 = idx0 + 256;
        int a0 = idx0 >> 10, c0 = idx0 & 1023;
        int a1 = idx1 >> 10, c1 = idx1 & 1023;
        const float* p0 = pred + (((size_t)(b * 425 + a0 * 85)) << 10) + c0;
        const float* p1 = pred + (((size_t)(b * 425 + a1 * 85)) << 10) + c1;
        // issue all global loads up front (latency hidden behind prep)
        float dx0 = p0[0], dy0 = p0[1024], tw0 = p0[2048], th0 = p0[3072], to0 = p0[4096];
        float dx1 = p1[0], dy1 = p1[1024], tw1 = p1[2048], th1 = p1[3072], to1 = p1[4096];

        flag[tid] = 0; flag[tid + 256] = 0;

        int mybb = -1;
        if (tid < NGT) {
            const float* g = gt + (size_t)(b * NGT + tid) * 7;
            float gdx = g[0], gdy = g[1], gx = g[2], gy = g[3], gw = g[4], gh = g[5];
            float ga = gw * gh;
            float best = -1.0f; int bp = 0;
            #pragma unroll
            for (int a = 0; a < 5; a++) {
                float aw = __ldg(&anc[2 * a]), ah = __ldg(&anc[2 * a + 1]);
                float it = fminf(gw, aw) * fminf(gh, ah);
                float iou = it / (ga + aw * ah - it);
                if (iou > best) { best = iou; bp = a; }
            }
            mybb = bp * 1024 + (int)gy * 32 + (int)gx;
            float cx = gdx + gx * (1.0f / 32.0f), cy = gdy + gy * (1.0f / 32.0f);
            sbox[tid] = make_float4(cx - 0.5f * gw, cy - 0.5f * gh, cx + 0.5f * gw, cy + 0.5f * gh);
            ssa6[tid] = 0.6f * ga;
        }
        __syncthreads();
        if (mybb >= base && mybb < base + 512) flag[mybb - base] = 1;

        // per-box params (no smem dependency — compute while waiting)
        float sdx0 = sigm(dx0), sdy0 = sigm(dy0), so0 = sigm(to0);
        float sdx1 = sigm(dx1), sdy1 = sigm(dy1), so1 = sigm(to1);
        float cx0 = sdx0 + (float)(c0 & 31) * (1.0f / 32.0f);
        float cy0 = sdy0 + (float)(c0 >> 5) * (1.0f / 32.0f);
        float cx1 = sdx1 + (float)(c1 & 31) * (1.0f / 32.0f);
        float cy1 = sdy1 + (float)(c1 >> 5) * (1.0f / 32.0f);
        float pw0 = __ldg(&anc[2 * a0]) * __expf(tw0), ph0 = __ldg(&anc[2 * a0 + 1]) * __expf(th0);
        float pw1 = __ldg(&anc[2 * a1]) * __expf(tw1), ph1 = __ldg(&anc[2 * a1 + 1]) * __expf(th1);
        float x10 = cx0 - 0.5f * pw0, y10 = cy0 - 0.5f * ph0, x20 = cx0 + 0.5f * pw0, y20 = cy0 + 0.5f * ph0;
        float x11 = cx1 - 0.5f * pw1, y11 = cy1 - 0.5f * ph1, x21 = cx1 + 0.5f * pw1, y21 = cy1 + 0.5f * ph1;
        float sb60 = 0.6f * pw0 * ph0, sb61 = 0.6f * pw1 * ph1;
        __syncthreads();

        // over-test:  iou > 0.6  <=>  1.6*inter - 0.6*sa > 0.6*sb   (division-free)
        float m0 = -1e30f, m1 = -1e30f;
        #pragma unroll 10
        for (int n = 0; n < NGT; n++) {
            float4 gb = sbox[n]; float s6 = ssa6[n];
            float w0 = fminf(x20, gb.z) - fmaxf(x10, gb.x);
            float h0 = fminf(y20, gb.w) - fmaxf(y10, gb.y);
            float i0 = fmaxf(w0, 0.0f) * fmaxf(h0, 0.0f);
            m0 = fmaxf(m0, fmaf(1.6f, i0, -s6));
            float w1 = fminf(x21, gb.z) - fmaxf(x11, gb.x);
            float h1 = fminf(y21, gb.w) - fmaxf(y11, gb.y);
            float i1 = fmaxf(w1, 0.0f) * fmaxf(h1, 0.0f);
            m1 = fmaxf(m1, fmaf(1.6f, i1, -s6));
        }
        bool ib0 = flag[tid] != 0, ib1 = flag[tid + 256] != 0;
        bool ov0 = m0 > sb60, ov1 = m1 > sb61;
        float no = ((!ib0 && !ov0) ? so0 * so0 : 0.0f) + ((!ib1 && !ov1) ? so1 * so1 : 0.0f);
        float pr = 0.0f;
        if (!ib0) { float d0 = sdx0 - 0.015625f, d1 = sdy0 - 0.015625f; pr += d0*d0 + d1*d1 + tw0*tw0 + th0*th0; }
        if (!ib1) { float d0 = sdx1 - 0.015625f, d1 = sdy1 - 0.015625f; pr += d0*d0 + d1*d1 + tw1*tw1 + th1*th1; }

        #pragma unroll
        for (int off = 16; off; off >>= 1) {
            no += __shfl_down_sync(0xffffffffu, no, off);
            pr += __shfl_down_sync(0xffffffffu, pr, off);
        }
        int wid = tid >> 5, lane = tid & 31;
        if (lane == 0) { sred[wid] = no; sred[8 + wid] = pr; }
        __syncthreads();
        if (tid == 0) {
            float s = 0.0f;
            #pragma unroll
            for (int i = 0; i < 8; i++) s += sred[i];
            g_noobj[blockIdx.x] = s;
        }
        if (tid == 32) {
            float s = 0.0f;
            #pragma unroll
            for (int i = 0; i < 8; i++) s += sred[8 + i];
            g_prior[blockIdx.x] = s;
        }
    } else {
        // ============== GATHER PATH: coord + obj + cls at 3200 best boxes ==============
        // 8 warps per 256-thread block, one GT per warp: 400 blocks x 8 = 3200 exactly.
        __shared__ float sc[8], so_[8], sl[8];
        int gb_ = blockIdx.x - MAIN_BLOCKS;
        int wid = tid >> 5, lane = tid & 31;
        int gtid = gb_ * 8 + wid;
        int b = gtid / NGT;

        const float* g = gt + (size_t)gtid * 7;   // broadcast loads across warp
        float gdx = g[0], gdy = g[1], gx = g[2], gy = g[3], gw = g[4], gh = g[5];
        int k = (int)g[6];
        float ga = gw * gh;
        float best = -1.0f; int bp = 0;
        #pragma unroll
        for (int a = 0; a < 5; a++) {
            float aw = __ldg(&anc[2 * a]), ah = __ldg(&anc[2 * a + 1]);
            float it = fminf(gw, aw) * fminf(gh, ah);
            float iou = it / (ga + aw * ah - it);
            if (iou > best) { best = iou; bp = a; }
        }
        int cell = (int)gy * 32 + (int)gx;
        const float* pp = pred + (((size_t)(b * 425 + bp * 85)) << 10) + cell;

        // one-pass softmax-MSE: sum_c (p_c - 1[c=k])^2 = Q/S^2 - 2 e_k/S + 1
        float S = 0.0f, Q = 0.0f, ek = 0.0f;
        {
            float e0 = __expf(pp[(size_t)(5 + lane) << 10]);  S += e0; Q += e0 * e0; if (lane == k) ek = e0;
            float e1 = __expf(pp[(size_t)(37 + lane) << 10]); S += e1; Q += e1 * e1; if (lane + 32 == k) ek = e1;
            if (lane < 16) {
                float e2 = __expf(pp[(size_t)(69 + lane) << 10]); S += e2; Q += e2 * e2; if (lane + 64 == k) ek = e2;
            }
        }
        #pragma unroll
        for (int off = 16; off; off >>= 1) {
            S  += __shfl_xor_sync(0xffffffffu, S,  off);
            Q  += __shfl_xor_sync(0xffffffffu, Q,  off);
            ek += __shfl_xor_sync(0xffffffffu, ek, off);
        }

        // uniform scalar part on all lanes (broadcast loads, no divergence)
        float sdx = sigm(pp[0]), sdy = sigm(pp[1024]);
        float tw = pp[2048], th = pp[3072], sobj = sigm(pp[4096]);
        float aw = __ldg(&anc[2 * bp]), ah = __ldg(&anc[2 * bp + 1]);
        float d0 = sdx - gdx, d1 = sdy - gdy;
        float d2 = tw - (__logf(gw) - __logf(aw));
        float d3 = th - (__logf(gh) - __logf(ah));
        float coord = d0*d0 + d1*d1 + d2*d2 + d3*d3;

        // exact IoU at this best box (only 3200 divisions in the whole kernel)
        float cx = sdx + (float)(cell & 31) * (1.0f / 32.0f);
        float cy = sdy + (float)(cell >> 5) * (1.0f / 32.0f);
        float pw = aw * __expf(tw), ph = ah * __expf(th);
        float gx1 = (gdx + gx * (1.0f / 32.0f)) - 0.5f * gw;
        float gy1 = (gdy + gy * (1.0f / 32.0f)) - 0.5f * gh;
        float w = fminf(cx + 0.5f * pw, gx1 + gw) - fmaxf(cx - 0.5f * pw, gx1);
        float h = fminf(cy + 0.5f * ph, gy1 + gh) - fmaxf(cy - 0.5f * ph, gy1);
        float inter = fmaxf(w, 0.0f) * fmaxf(h, 0.0f);
        float iou_t = inter / (ga + pw * ph - inter);
        float di = sobj - iou_t;
        float obj = di * di;
        float invS = 1.0f / S;
        float cls = fmaf(Q * invS, invS, fmaf(-2.0f * ek, invS, 1.0f));

        if (lane == 0) { sc[wid] = coord; so_[wid] = obj; sl[wid] = cls; }
        __syncthreads();
        if (tid == 0) {
            float tc = 0.f, to_ = 0.f, tl = 0.f;
            #pragma unroll
            for (int i = 0; i < 8; i++) { tc += sc[i]; to_ += so_[i]; tl += sl[i]; }
            g_coord[gb_] = tc;
            g_obj[gb_]   = to_;
            g_cls[gb_]   = tl;
        }
    }
}

// ---------------- deterministic final combine (single lean block) ----------------
__global__ void __launch_bounds__(256) final_kernel(float* __restrict__ out,
                                                    const int* __restrict__ seen)
{
    __shared__ float sm[40];
    int tid = threadIdx.x;
    float a0 = 0.f, a1 = 0.f, a2 = 0.f, a3 = 0.f, a4 = 0.f;
    for (int i = tid; i < MAIN_BLOCKS; i += 256) { a0 += g_noobj[i]; a1 += g_prior[i]; }
    for (int i = tid; i < GATH_BLOCKS; i += 256) { a2 += g_coord[i]; a3 += g_obj[i]; a4 += g_cls[i]; }
    #pragma unroll
    for (int off = 16; off; off >>= 1) {
        a0 += __shfl_down_sync(0xffffffffu, a0, off);
        a1 += __shfl_down_sync(0xffffffffu, a1, off);
        a2 += __shfl_down_sync(0xffffffffu, a2, off);
        a3 += __shfl_down_sync(0xffffffffu, a3, off);
        a4 += __shfl_down_sync(0xffffffffu, a4, off);
    }
    int wid = tid >> 5, lane = tid & 31;
    if (lane == 0) {
        sm[wid] = a0; sm[8 + wid] = a1; sm[16 + wid] = a2; sm[24 + wid] = a3; sm[32 + wid] = a4;
    }
    __syncthreads();
    if (tid == 0) {
        float t0 = 0.f, t1 = 0.f, t2 = 0.f, t3 = 0.f, t4 = 0.f;
        #pragma unroll
        for (int i = 0; i < 8; i++) {
            t0 += sm[i]; t1 += sm[8 + i]; t2 += sm[16 + i]; t3 += sm[24 + i]; t4 += sm[32 + i];
        }
        float lp = (seen[0] < 12800) ? 0.01f : 0.0f;
        // loss = cls + noobj + 5*obj + coord + 0.01*prior(if seen<thr)
        out[0] = t4 + t0 + 5.0f * t3 + t2 + lp * t1;
    }
}

extern "C" void kernel_launch(void* const* d_in, const int* in_sizes, int n_in,
                              void* d_out, int out_size) {
    const float* pred = (const float*)d_in[0];
    const float* gt   = (const float*)d_in[1];
    const float* anc  = (const float*)d_in[2];
    const int*   seen = (const int*)d_in[3];
    (void)in_sizes; (void)n_in; (void)out_size;

    fused_kernel<<<TOTAL_BLOCKS, 256>>>(pred, gt, anc);
    final_kernel<<<1, 256>>>((float*)d_out, seen);
}